// round 17
// baseline (speedup 1.0000x reference)
#include <cuda_runtime.h>
#include <cstdint>

#define NN 8192
#define DD 64
#define EPSF 1e-6f
#define PITCH_W 36   // 32-bit words per smem row (144B): conflict-free frags
#define T_U 0.0625f
#define L2E 1.44269504f
#define LN2 0.69314718f
#define SQRT2_L2E 2.04027891f   // sqrt(2) * log2(e)
#define GRID_BLOCKS (128 * 64)

// scratch (no allocations allowed)
__device__ double g_acc = 0.0;
__device__ unsigned int g_ctr = 0;

__device__ __forceinline__ uint32_t pack_bf16x2(float lo, float hi) {
    uint32_t r;
    asm("cvt.rn.bf16x2.f32 %0, %1, %2;" : "=r"(r) : "f"(hi), "f"(lo));
    return r;
}
__device__ __forceinline__ float sqrt_approx(float x) {
    float r; asm("sqrt.approx.f32 %0, %1;" : "=f"(r) : "f"(x)); return r;
}
__device__ __forceinline__ float ex2f(float x) {
    float r; asm("ex2.approx.f32 %0, %1;" : "=f"(r) : "f"(x)); return r;
}

// ---------------------------------------------------------------------------
// single fused kernel: bf16 mma.sync gram (tile 128 x 64, K=64).
// Per-block row stats computed from the fp32 staging loads (exact fp32).
// Zj staged NEGATED; accumulator init = 0.5pi + 0.5q -> acc = d^2/2.
// Linear softplus + ballot-gated exact correction. Last block emits scalar.
// ---------------------------------------------------------------------------
__global__ __launch_bounds__(128) void lsm_main(const int* __restrict__ A,
                                                const float* __restrict__ Z,
                                                const float* __restrict__ alpha,
                                                float* __restrict__ out) {
    extern __shared__ __align__(16) uint32_t smem[];
    uint32_t* s_zi = smem;                        // [128][PITCH_W]
    uint32_t* s_zj = smem + 128 * PITCH_W;        // [64][PITCH_W], negated
    float* s_pi = (float*)(s_zj + 64 * PITCH_W);  // [128] pi_half
    float* s_qh = s_pi + 128;                     // [64] q_half
    float* s_qy = s_qh + 64;                      // [64] alpha_j * L2E
    float* s_ws = s_qy + 64;                      // [4]

    const int tid = (int)threadIdx.x;
    const int wid = tid >> 5, lane = tid & 31;
    const int g = lane >> 2, t = lane & 3;
    const int bi = blockIdx.y, bj = blockIdx.x;   // rows bi*128, cols bj*64
    const int wm = wid * 32;
    const bool diagblk = ((bj >> 1) == bi);

    if (tid < 64) s_qy[tid] = alpha[bj * 64 + tid] * L2E;

    // ---- stage Z tiles as bf16 AND compute exact fp32 row stats ----
    // idx = it*128+tid: 16 consecutive tids share a row (k4 = tid&15).
    {
        const float4* src = (const float4*)(Z + (size_t)(bi * 128) * DD);
#pragma unroll
        for (int it = 0; it < 16; ++it) {
            int idx = it * 128 + tid;
            int r = idx >> 4, k4 = idx & 15;
            float4 v = src[(size_t)r * 16 + k4];
            *(uint2*)(s_zi + r * PITCH_W + k4 * 2) =
                make_uint2(pack_bf16x2(v.x, v.y), pack_bf16x2(v.z, v.w));
            float s = (v.x + v.y) + (v.z + v.w);
            float sq = fmaf(v.x, v.x, v.y * v.y) + fmaf(v.z, v.z, v.w * v.w);
#pragma unroll
            for (int off = 8; off; off >>= 1) {
                s  += __shfl_xor_sync(0xffffffffu, s, off);
                sq += __shfl_xor_sync(0xffffffffu, sq, off);
            }
            if ((lane & 15) == 0)
                s_pi[r] = 0.5f * (sq + 2.0f * EPSF * s +
                                  (float)DD * EPSF * EPSF);
        }
        const float4* srcj = (const float4*)(Z + (size_t)(bj * 64) * DD);
#pragma unroll
        for (int it = 0; it < 8; ++it) {
            int idx = it * 128 + tid;
            int r = idx >> 4, k4 = idx & 15;
            float4 v = srcj[(size_t)r * 16 + k4];
            *(uint2*)(s_zj + r * PITCH_W + k4 * 2) =
                make_uint2(pack_bf16x2(v.x, v.y) ^ 0x80008000u,
                           pack_bf16x2(v.z, v.w) ^ 0x80008000u);
            float s = (v.x + v.y) + (v.z + v.w);
            float sq = fmaf(v.x, v.x, v.y * v.y) + fmaf(v.z, v.z, v.w * v.w);
#pragma unroll
            for (int off = 8; off; off >>= 1) {
                s  += __shfl_xor_sync(0xffffffffu, s, off);
                sq += __shfl_xor_sync(0xffffffffu, sq, off);
            }
            if ((lane & 15) == 0)
                s_qh[r] = 0.5f * (sq - 2.0f * EPSF * s);
        }
    }
    __syncthreads();

    // ---- preload ALL a-fragments (K=64 -> 4 k16-steps) ----
    uint32_t a[4][2][4];
#pragma unroll
    for (int ks = 0; ks < 4; ++ks)
#pragma unroll
        for (int mf = 0; mf < 2; ++mf) {
            int r0 = wm + mf * 16 + g;
            const uint32_t* base = s_zi + ks * 8 + t;
            a[ks][mf][0] = base[r0 * PITCH_W];
            a[ks][mf][1] = base[(r0 + 8) * PITCH_W];
            a[ks][mf][2] = base[r0 * PITCH_W + 4];
            a[ks][mf][3] = base[(r0 + 8) * PITCH_W + 4];
        }

    // per-thread row constants (half-pi) + A row pointers
    float pir[4];
    const int2* ar[4];
#pragma unroll
    for (int mf = 0; mf < 2; ++mf)
#pragma unroll
        for (int rs = 0; rs < 2; ++rs) {
            int r = mf * 2 + rs;
            int i_loc = wm + mf * 16 + rs * 8 + g;
            pir[r] = s_pi[i_loc];
            ar[r] = (const int2*)(A + (size_t)(bi * 128 + i_loc) * NN + bj * 64);
        }

    float llA = 0.0f;    // sum of A_ij * theta (log2 units)
    float llS = 0.0f;    // sum of softplus-linear terms
    float acc0[2][4], acc1[2][4];

#define DO_MMA(NF, ACC)                                                        \
    do {                                                                       \
        float qh0 = s_qh[(NF) * 8 + 2 * t];                                    \
        float qh1 = s_qh[(NF) * 8 + 2 * t + 1];                                \
        _Pragma("unroll")                                                      \
        for (int mf = 0; mf < 2; ++mf) {                                       \
            ACC[mf][0] = pir[mf * 2] + qh0;                                    \
            ACC[mf][1] = pir[mf * 2] + qh1;                                    \
            ACC[mf][2] = pir[mf * 2 + 1] + qh0;                                \
            ACC[mf][3] = pir[mf * 2 + 1] + qh1;                                \
        }                                                                      \
        _Pragma("unroll")                                                      \
        for (int ks = 0; ks < 4; ++ks) {                                       \
            int c0 = (NF) * 8 + g;                                             \
            uint32_t b0 = s_zj[c0 * PITCH_W + ks * 8 + t];                     \
            uint32_t b1 = s_zj[c0 * PITCH_W + ks * 8 + t + 4];                 \
            _Pragma("unroll")                                                  \
            for (int mf = 0; mf < 2; ++mf) {                                   \
                asm volatile(                                                  \
                    "mma.sync.aligned.m16n8k16.row.col.f32.bf16.bf16.f32 "     \
                    "{%0,%1,%2,%3}, {%4,%5,%6,%7}, {%8,%9}, {%0,%1,%2,%3};"    \
                    : "+f"(ACC[mf][0]), "+f"(ACC[mf][1]),                      \
                      "+f"(ACC[mf][2]), "+f"(ACC[mf][3])                       \
                    : "r"(a[ks][mf][0]), "r"(a[ks][mf][1]),                    \
                      "r"(a[ks][mf][2]), "r"(a[ks][mf][3]),                    \
                      "r"(b0), "r"(b1));                                       \
            }                                                                  \
        }                                                                      \
    } while (0)

#define DO_EPI(NF, ACC)                                                        \
    do {                                                                       \
        float uarr[8];                                                         \
        float umax = 0.0f;                                                     \
        float qy0 = s_qy[(NF) * 8 + 2 * t];                                    \
        float qy1 = s_qy[(NF) * 8 + 2 * t + 1];                                \
        _Pragma("unroll")                                                      \
        for (int mf = 0; mf < 2; ++mf)                                         \
            _Pragma("unroll")                                                  \
            for (int rs = 0; rs < 2; ++rs) {                                   \
                int r = mf * 2 + rs;                                           \
                int2 a2 = ar[r][(NF) * 4 + t];                                 \
                float z0 = sqrt_approx(fmaxf(ACC[mf][rs * 2 + 0], 0.0f));      \
                float z1 = sqrt_approx(fmaxf(ACC[mf][rs * 2 + 1], 0.0f));      \
                float thl0 = fmaf(z0, -SQRT2_L2E, qy0);                        \
                float thl1 = fmaf(z1, -SQRT2_L2E, qy1);                        \
                float u0 = ex2f(thl0);                                         \
                float u1 = ex2f(thl1);                                         \
                uarr[r * 2] = u0; uarr[r * 2 + 1] = u1;                        \
                umax = fmaxf(umax, fmaxf(u0, u1));                             \
                llS += u0 + u1;                                                \
                if (a2.x) llA += thl0;                                         \
                if (a2.y) llA += thl1;                                         \
            }                                                                  \
        if (__any_sync(0xffffffffu, umax > T_U)) {  /* ~never off-diag */      \
            _Pragma("unroll")                                                  \
            for (int e = 0; e < 8; ++e)                                        \
                if (uarr[e] > T_U)                                             \
                    llS += __logf(1.0f + uarr[e]) - uarr[e];                   \
        }                                                                      \
        if (diagblk) {                                                         \
            _Pragma("unroll")                                                  \
            for (int mf = 0; mf < 2; ++mf)                                     \
                _Pragma("unroll")                                              \
                for (int rs = 0; rs < 2; ++rs)                                 \
                    _Pragma("unroll")                                          \
                    for (int c = 0; c < 2; ++c) {                              \
                        int i_loc = wm + mf * 16 + rs * 8 + g;                 \
                        int ig = bi * 128 + i_loc;                             \
                        int jg = bj * 64 + (NF) * 8 + 2 * t + c;               \
                        if (ig == jg) {                                        \
                            float u = uarr[(mf * 2 + rs) * 2 + c];             \
                            /* subtract exactly what the main path added */    \
                            llS -= (u > T_U) ? __logf(1.0f + u) : u;           \
                        }                                                      \
                    }                                                          \
        }                                                                      \
    } while (0)

    // ---- skewed pipeline: MMA(nf) overlaps epilogue(nf-1) ----
    DO_MMA(0, acc0);
    DO_MMA(1, acc1);  DO_EPI(0, acc0);
    DO_MMA(2, acc0);  DO_EPI(1, acc1);
    DO_MMA(3, acc1);  DO_EPI(2, acc0);
    DO_MMA(4, acc0);  DO_EPI(3, acc1);
    DO_MMA(5, acc1);  DO_EPI(4, acc0);
    DO_MMA(6, acc0);  DO_EPI(5, acc1);
    DO_MMA(7, acc1);  DO_EPI(6, acc0);
    DO_EPI(7, acc1);

    float ll = 0.5f * (fmaf(llA, LN2, -llS));

    // ---- reduce + single double atomic per block ----
#pragma unroll
    for (int off = 16; off; off >>= 1) ll += __shfl_xor_sync(0xffffffffu, ll, off);
    if (lane == 0) s_ws[wid] = ll;
    __syncthreads();

    __shared__ int is_last;
    if (tid == 0) {
        atomicAdd(&g_acc, (double)(s_ws[0] + s_ws[1] + s_ws[2] + s_ws[3]));
        __threadfence();
        unsigned prev = atomicInc(&g_ctr, GRID_BLOCKS - 1); // wraps to 0
        is_last = (prev == GRID_BLOCKS - 1);
    }
    __syncthreads();
    if (is_last && tid == 0) {
        __threadfence();
        double total = atomicAdd(&g_acc, 0.0);   // fresh read
        out[0] = (float)total;
        g_acc = 0.0;                              // reset for next call
    }
}

// ---------------------------------------------------------------------------
extern "C" void kernel_launch(void* const* d_in, const int* in_sizes, int n_in,
                              void* d_out, int out_size) {
    const int* A = nullptr;
    const float* alpha = nullptr;
    const float* Z = nullptr;
    for (int i = 0; i < n_in; ++i) {
        if (in_sizes[i] == NN) alpha = (const float*)d_in[i];
        else if (in_sizes[i] == NN * DD) Z = (const float*)d_in[i];
        else A = (const int*)d_in[i];
    }

    const int smem_bytes = (128 * PITCH_W + 64 * PITCH_W + 128 + 64 + 64 + 4) * 4;
    cudaFuncSetAttribute(lsm_main, cudaFuncAttributeMaxDynamicSharedMemorySize,
                         smem_bytes);

    dim3 grid(NN / 64, NN / 128);   // 128 x 64 = GRID_BLOCKS
    lsm_main<<<grid, 128, smem_bytes>>>(A, Z, alpha, (float*)d_out);
}